// round 12
// baseline (speedup 1.0000x reference)
#include <cuda_runtime.h>

#define DIMN 128
#define NH   8
#define MAXN 50000
#define MAXE 800000
#define SROW 132                 // smem row stride in floats (padded)
#define PROJ_SMEM (2 * 128 * SROW * 4)

// Scratch (device globals: no allocation allowed)
__device__ float g_q[MAXN * DIMN];
__device__ float g_k[MAXN * DIMN];
__device__ float g_v[MAXN * DIMN];
__device__ float g_agg[MAXN * DIMN];   // normalized attention output
__device__ int   g_cnt[MAXN];          // per-target edge counts
__device__ int   g_off[MAXN + 1];      // CSR row offsets
__device__ int   g_cur[MAXN];          // scatter cursors
__device__ int   g_srcs[MAXE];         // CSR: src node per edge, grouped by tgt

// ---------------------------------------------------------------------------
// packed f32x2 helpers (sm_100+)
// ---------------------------------------------------------------------------
__device__ __forceinline__ unsigned long long pack2(float x, float y)
{
    unsigned long long r;
    asm("mov.b64 %0, {%1, %2};" : "=l"(r) : "f"(x), "f"(y));
    return r;
}
__device__ __forceinline__ void unpack2(unsigned long long v, float& x, float& y)
{
    asm("mov.b64 {%0, %1}, %2;" : "=f"(x), "=f"(y) : "l"(v));
}
__device__ __forceinline__ unsigned long long fma2(unsigned long long a,
                                                   unsigned long long b,
                                                   unsigned long long c)
{
    unsigned long long d;
    asm("fma.rn.f32x2 %0, %1, %2, %3;" : "=l"(d) : "l"(a), "l"(b), "l"(c));
    return d;
}

// smem word offset for element [k][c] of a transposed 128x128 tile,
// XOR-swizzled at float4 granularity.
__device__ __forceinline__ int sw_off(int k, int c4, int c3)
{
    int f = ((k >> 2) + (k >> 5)) & 7;
    return k * SROW + ((c4 ^ f) << 2) + c3;
}

// ---------------------------------------------------------------------------
// init: counts = 0
// ---------------------------------------------------------------------------
__global__ void init_kernel(int n)
{
    int i = blockIdx.x * blockDim.x + threadIdx.x;
    if (i < n) g_cnt[i] = 0;
}

// ---------------------------------------------------------------------------
// CSR build: histogram -> scan -> scatter
// ---------------------------------------------------------------------------
__global__ void hist_kernel(const int* __restrict__ ei, int E)
{
    int e = blockIdx.x * blockDim.x + threadIdx.x;
    if (e < E) atomicAdd(&g_cnt[__ldg(&ei[e])], 1);
}

__global__ void __launch_bounds__(1024) scan_kernel(int n)
{
    __shared__ int ssum[1024];
    int t = threadIdx.x;
    int chunk = (n + 1023) >> 10;
    int beg = t * chunk, end = min(beg + chunk, n);
    int s = 0;
    for (int i = beg; i < end; i++) s += g_cnt[i];
    ssum[t] = s;
    __syncthreads();
    for (int d = 1; d < 1024; d <<= 1) {
        int v = (t >= d) ? ssum[t - d] : 0;
        __syncthreads();
        ssum[t] += v;
        __syncthreads();
    }
    int base = (t == 0) ? 0 : ssum[t - 1];
    for (int i = beg; i < end; i++) {
        g_off[i] = base;
        g_cur[i] = base;
        base += g_cnt[i];
    }
    if (t == 1023) g_off[n] = ssum[1023];
}

__global__ void scatter_kernel(const int* __restrict__ ei, int E)
{
    int e = blockIdx.x * blockDim.x + threadIdx.x;
    if (e >= E) return;
    int tgt = __ldg(&ei[e]);
    int src = __ldg(&ei[E + e]);
    int pos = atomicAdd(&g_cur[tgt], 1);
    g_srcs[pos] = src;
}

// ---------------------------------------------------------------------------
// Tiled SGEMM body: out[r,c] = sum_k x[r,k] * W[c,k] + b[c]   (x @ W^T + b)
// Block: 256 threads (16x16), tile 128x128, 8x8 microtile, f32x2 accum.
// ---------------------------------------------------------------------------
__device__ __forceinline__ void proj_body(
    const float* __restrict__ x, const float* __restrict__ W,
    const float* __restrict__ bias, float* __restrict__ out, int n,
    float* ws, float* xs)
{
    const int tid  = threadIdx.x;
    const int base = blockIdx.x * 128;

    {
        const int lane = tid & 31;
        const int cw   = tid >> 5;
        const int k0   = lane * 4;
        for (int c = cw; c < 128; c += 8) {
            float4 w = __ldg((const float4*)(W + c * 128) + lane);
            int c4 = c >> 2, c3 = c & 3;
            ws[sw_off(k0 + 0, c4, c3)] = w.x;
            ws[sw_off(k0 + 1, c4, c3)] = w.y;
            ws[sw_off(k0 + 2, c4, c3)] = w.z;
            ws[sw_off(k0 + 3, c4, c3)] = w.w;

            int gr = base + c;
            float4 xv = (gr < n) ? __ldg((const float4*)(x + (size_t)gr * 128) + lane)
                                 : make_float4(0.f, 0.f, 0.f, 0.f);
            xs[sw_off(k0 + 0, c4, c3)] = xv.x;
            xs[sw_off(k0 + 1, c4, c3)] = xv.y;
            xs[sw_off(k0 + 2, c4, c3)] = xv.z;
            xs[sw_off(k0 + 3, c4, c3)] = xv.w;
        }
    }
    __syncthreads();

    const int tx = tid & 15;
    const int ty = tid >> 4;

    unsigned long long acc[4][8];
#pragma unroll
    for (int i = 0; i < 4; i++)
#pragma unroll
        for (int j = 0; j < 8; j++) acc[i][j] = 0ULL;

#pragma unroll 16
    for (int k = 0; k < 128; k++) {
        int f  = ((k >> 2) + (k >> 5)) & 7;
        int ro = k * SROW;
        ulonglong2 a01 = *(const ulonglong2*)(xs + ro + ((((ty * 2 + 0) ^ f)) << 2));
        ulonglong2 a23 = *(const ulonglong2*)(xs + ro + ((((ty * 2 + 1) ^ f)) << 2));
        float4 w0 = *(const float4*)(ws + ro + ((((tx * 2 + 0) ^ f)) << 2));
        float4 w1 = *(const float4*)(ws + ro + ((((tx * 2 + 1) ^ f)) << 2));
        unsigned long long aa[4] = { a01.x, a01.y, a23.x, a23.y };
        unsigned long long bb[8];
        bb[0] = pack2(w0.x, w0.x); bb[1] = pack2(w0.y, w0.y);
        bb[2] = pack2(w0.z, w0.z); bb[3] = pack2(w0.w, w0.w);
        bb[4] = pack2(w1.x, w1.x); bb[5] = pack2(w1.y, w1.y);
        bb[6] = pack2(w1.z, w1.z); bb[7] = pack2(w1.w, w1.w);
#pragma unroll
        for (int i = 0; i < 4; i++)
#pragma unroll
            for (int j = 0; j < 8; j++)
                acc[i][j] = fma2(aa[i], bb[j], acc[i][j]);
    }

    float4 b0 = __ldg((const float4*)bias + tx * 2);
    float4 b1 = __ldg((const float4*)bias + tx * 2 + 1);
#pragma unroll
    for (int i = 0; i < 4; i++) {
        int r0 = base + ty * 8 + i * 2;
        float lo[8], hi[8];
#pragma unroll
        for (int j = 0; j < 8; j++) unpack2(acc[i][j], lo[j], hi[j]);
        if (r0 < n) {
            float4 o0 = make_float4(lo[0] + b0.x, lo[1] + b0.y, lo[2] + b0.z, lo[3] + b0.w);
            float4 o1 = make_float4(lo[4] + b1.x, lo[5] + b1.y, lo[6] + b1.z, lo[7] + b1.w);
            float4* op = (float4*)(out + (size_t)r0 * 128);
            op[tx * 2] = o0; op[tx * 2 + 1] = o1;
        }
        if (r0 + 1 < n) {
            float4 o0 = make_float4(hi[0] + b0.x, hi[1] + b0.y, hi[2] + b0.z, hi[3] + b0.w);
            float4 o1 = make_float4(hi[4] + b1.x, hi[5] + b1.y, hi[6] + b1.z, hi[7] + b1.w);
            float4* op = (float4*)(out + (size_t)(r0 + 1) * 128);
            op[tx * 2] = o0; op[tx * 2 + 1] = o1;
        }
    }
}

__global__ void __launch_bounds__(256, 1) proj3_kernel(
    const float* __restrict__ x,
    const float* __restrict__ Wq, const float* __restrict__ bq,
    const float* __restrict__ Wk, const float* __restrict__ bk,
    const float* __restrict__ Wv, const float* __restrict__ bv, int n)
{
    extern __shared__ float sm[];
    const float *W, *b; float* o;
    if (blockIdx.y == 0)      { W = Wq; b = bq; o = g_q; }
    else if (blockIdx.y == 1) { W = Wk; b = bk; o = g_k; }
    else                      { W = Wv; b = bv; o = g_v; }
    proj_body(x, W, b, o, n, sm, sm + 128 * SROW);
}

__global__ void __launch_bounds__(256, 1) projo_kernel(
    const float* __restrict__ W, const float* __restrict__ b,
    float* __restrict__ out, int n)
{
    extern __shared__ float sm[];
    proj_body(g_agg, W, b, out, n, sm, sm + 128 * SROW);
}

// ---------------------------------------------------------------------------
// node aggregation: one warp per target node, edges from CSR.
//   p_h = exp(q[src,h]·k[tgt,h]/4);  acc += p*v[src];  s_h += p
//   g_agg[tgt] = acc / s  (per head) — no atomics, single write.
// Lane owns float4 j; quad (4 lanes) = one head; shfl-quad-reduce for dots.
// ---------------------------------------------------------------------------
__global__ void __launch_bounds__(256) node_kernel(int n)
{
    int w = (blockIdx.x * blockDim.x + threadIdx.x) >> 5;
    if (w >= n) return;
    int lane = threadIdx.x & 31;

    int beg = __ldg(&g_off[w]);
    int end = __ldg(&g_off[w + 1]);

    float4 kv = __ldg(((const float4*)&g_k[(size_t)w * DIMN]) + lane);

    float4 acc = make_float4(0.f, 0.f, 0.f, 0.f);
    float ssum = 0.f;

#pragma unroll 2
    for (int i = beg; i < end; i++) {
        int src = __ldg(&g_srcs[i]);
        const float4* qp = ((const float4*)&g_q[(size_t)src * DIMN]) + lane;
        const float4* vp = ((const float4*)&g_v[(size_t)src * DIMN]) + lane;
        float4 qv = __ldg(qp);
        float s4 = qv.x * kv.x + qv.y * kv.y + qv.z * kv.z + qv.w * kv.w;
        s4 += __shfl_xor_sync(0xFFFFFFFFu, s4, 1);
        s4 += __shfl_xor_sync(0xFFFFFFFFu, s4, 2);   // quad-wide head dot

        float p = __expf(s4 * 0.25f);                // 1/sqrt(HD=16)
        ssum += p;

        float4 vv = __ldg(vp);
        acc.x += p * vv.x; acc.y += p * vv.y;
        acc.z += p * vv.z; acc.w += p * vv.w;
    }

    float inv = (ssum > 0.f) ? __frcp_rn(ssum) : 0.f;
    float4 o = make_float4(acc.x * inv, acc.y * inv, acc.z * inv, acc.w * inv);
    ((float4*)&g_agg[(size_t)w * DIMN])[lane] = o;
}

// ---------------------------------------------------------------------------
extern "C" void kernel_launch(void* const* d_in, const int* in_sizes, int n_in,
                              void* d_out, int out_size)
{
    const float* x   = (const float*)d_in[0];
    const int*   ei  = (const int*)d_in[1];
    const float* Wq  = (const float*)d_in[2];
    const float* bq  = (const float*)d_in[3];
    const float* Wk  = (const float*)d_in[4];
    const float* bk  = (const float*)d_in[5];
    const float* Wv  = (const float*)d_in[6];
    const float* bv  = (const float*)d_in[7];
    const float* Wo  = (const float*)d_in[8];
    const float* bo  = (const float*)d_in[9];
    float*       out = (float*)d_out;

    int n = in_sizes[0] / DIMN;
    int E = in_sizes[1] / 2;

    cudaFuncSetAttribute(proj3_kernel, cudaFuncAttributeMaxDynamicSharedMemorySize, PROJ_SMEM);
    cudaFuncSetAttribute(projo_kernel, cudaFuncAttributeMaxDynamicSharedMemorySize, PROJ_SMEM);

    // CSR build (independent of projections)
    init_kernel<<<(n + 255) / 256, 256>>>(n);
    hist_kernel<<<(E + 255) / 256, 256>>>(ei, E);
    scan_kernel<<<1, 1024>>>(n);
    scatter_kernel<<<(E + 255) / 256, 256>>>(ei, E);

    // projections
    int pblocks = (n + 127) / 128;
    proj3_kernel<<<dim3(pblocks, 3), 256, PROJ_SMEM>>>(x, Wq, bq, Wk, bk, Wv, bv, n);

    // per-node attention aggregation (no atomics)
    node_kernel<<<(n * 32 + 255) / 256, 256>>>(n);

    projo_kernel<<<pblocks, 256, PROJ_SMEM>>>(Wo, bo, out, n);
}

// round 13
// speedup vs baseline: 1.0389x; 1.0389x over previous
#include <cuda_runtime.h>

#define DIMN 128
#define NH   8
#define MAXN 50000
#define MAXE 800000
#define SROW 132                 // smem row stride in floats (padded)
#define PROJ_SMEM (2 * 128 * SROW * 4)

// Scratch (device globals: no allocation allowed)
__device__ float g_q[MAXN * DIMN];
__device__ float g_k[MAXN * DIMN];
__device__ float g_v[MAXN * DIMN];
__device__ float g_agg[MAXN * DIMN];   // normalized attention output
__device__ int   g_cnt[MAXN];          // per-target edge counts
__device__ int   g_off[MAXN + 1];      // CSR row offsets
__device__ int   g_cur[MAXN];          // scatter cursors
__device__ int   g_srcs[MAXE];         // CSR: src node per edge, grouped by tgt

// ---------------------------------------------------------------------------
// packed f32x2 helpers (sm_100+)
// ---------------------------------------------------------------------------
__device__ __forceinline__ unsigned long long pack2(float x, float y)
{
    unsigned long long r;
    asm("mov.b64 %0, {%1, %2};" : "=l"(r) : "f"(x), "f"(y));
    return r;
}
__device__ __forceinline__ void unpack2(unsigned long long v, float& x, float& y)
{
    asm("mov.b64 {%0, %1}, %2;" : "=f"(x), "=f"(y) : "l"(v));
}
__device__ __forceinline__ unsigned long long fma2(unsigned long long a,
                                                   unsigned long long b,
                                                   unsigned long long c)
{
    unsigned long long d;
    asm("fma.rn.f32x2 %0, %1, %2, %3;" : "=l"(d) : "l"(a), "l"(b), "l"(c));
    return d;
}

// smem word offset for element [k][c] of a transposed 128x128 tile,
// XOR-swizzled at float4 granularity.
__device__ __forceinline__ int sw_off(int k, int c4, int c3)
{
    int f = ((k >> 2) + (k >> 5)) & 7;
    return k * SROW + ((c4 ^ f) << 2) + c3;
}

// ---------------------------------------------------------------------------
// init: counts = 0
// ---------------------------------------------------------------------------
__global__ void init_kernel(int n)
{
    int i = blockIdx.x * blockDim.x + threadIdx.x;
    if (i < n) g_cnt[i] = 0;
}

// ---------------------------------------------------------------------------
// CSR build: histogram -> scan -> scatter
// ---------------------------------------------------------------------------
__global__ void hist_kernel(const int* __restrict__ ei, int E)
{
    int e = blockIdx.x * blockDim.x + threadIdx.x;
    if (e < E) atomicAdd(&g_cnt[__ldg(&ei[e])], 1);
}

__global__ void __launch_bounds__(1024) scan_kernel(int n)
{
    __shared__ int ssum[1024];
    int t = threadIdx.x;
    int chunk = (n + 1023) >> 10;
    int beg = t * chunk, end = min(beg + chunk, n);
    int s = 0;
    for (int i = beg; i < end; i++) s += g_cnt[i];
    ssum[t] = s;
    __syncthreads();
    for (int d = 1; d < 1024; d <<= 1) {
        int v = (t >= d) ? ssum[t - d] : 0;
        __syncthreads();
        ssum[t] += v;
        __syncthreads();
    }
    int base = (t == 0) ? 0 : ssum[t - 1];
    for (int i = beg; i < end; i++) {
        g_off[i] = base;
        g_cur[i] = base;
        base += g_cnt[i];
    }
    if (t == 1023) g_off[n] = ssum[1023];
}

__global__ void scatter_kernel(const int* __restrict__ ei, int E)
{
    int e = blockIdx.x * blockDim.x + threadIdx.x;
    if (e >= E) return;
    int tgt = __ldg(&ei[e]);
    int src = __ldg(&ei[E + e]);
    int pos = atomicAdd(&g_cur[tgt], 1);
    g_srcs[pos] = src;
}

// ---------------------------------------------------------------------------
// Tiled SGEMM body: out[r,c] = sum_k x[r,k] * W[c,k] + b[c]   (x @ W^T + b)
// Block: 256 threads (16x16), tile 128x128, 8x8 microtile, f32x2 accum.
// ---------------------------------------------------------------------------
__device__ __forceinline__ void proj_body(
    const float* __restrict__ x, const float* __restrict__ W,
    const float* __restrict__ bias, float* __restrict__ out, int n,
    float* ws, float* xs)
{
    const int tid  = threadIdx.x;
    const int base = blockIdx.x * 128;

    {
        const int lane = tid & 31;
        const int cw   = tid >> 5;
        const int k0   = lane * 4;
        for (int c = cw; c < 128; c += 8) {
            float4 w = __ldg((const float4*)(W + c * 128) + lane);
            int c4 = c >> 2, c3 = c & 3;
            ws[sw_off(k0 + 0, c4, c3)] = w.x;
            ws[sw_off(k0 + 1, c4, c3)] = w.y;
            ws[sw_off(k0 + 2, c4, c3)] = w.z;
            ws[sw_off(k0 + 3, c4, c3)] = w.w;

            int gr = base + c;
            float4 xv = (gr < n) ? __ldg((const float4*)(x + (size_t)gr * 128) + lane)
                                 : make_float4(0.f, 0.f, 0.f, 0.f);
            xs[sw_off(k0 + 0, c4, c3)] = xv.x;
            xs[sw_off(k0 + 1, c4, c3)] = xv.y;
            xs[sw_off(k0 + 2, c4, c3)] = xv.z;
            xs[sw_off(k0 + 3, c4, c3)] = xv.w;
        }
    }
    __syncthreads();

    const int tx = tid & 15;
    const int ty = tid >> 4;

    unsigned long long acc[4][8];
#pragma unroll
    for (int i = 0; i < 4; i++)
#pragma unroll
        for (int j = 0; j < 8; j++) acc[i][j] = 0ULL;

#pragma unroll 16
    for (int k = 0; k < 128; k++) {
        int f  = ((k >> 2) + (k >> 5)) & 7;
        int ro = k * SROW;
        ulonglong2 a01 = *(const ulonglong2*)(xs + ro + ((((ty * 2 + 0) ^ f)) << 2));
        ulonglong2 a23 = *(const ulonglong2*)(xs + ro + ((((ty * 2 + 1) ^ f)) << 2));
        float4 w0 = *(const float4*)(ws + ro + ((((tx * 2 + 0) ^ f)) << 2));
        float4 w1 = *(const float4*)(ws + ro + ((((tx * 2 + 1) ^ f)) << 2));
        unsigned long long aa[4] = { a01.x, a01.y, a23.x, a23.y };
        unsigned long long bb[8];
        bb[0] = pack2(w0.x, w0.x); bb[1] = pack2(w0.y, w0.y);
        bb[2] = pack2(w0.z, w0.z); bb[3] = pack2(w0.w, w0.w);
        bb[4] = pack2(w1.x, w1.x); bb[5] = pack2(w1.y, w1.y);
        bb[6] = pack2(w1.z, w1.z); bb[7] = pack2(w1.w, w1.w);
#pragma unroll
        for (int i = 0; i < 4; i++)
#pragma unroll
            for (int j = 0; j < 8; j++)
                acc[i][j] = fma2(aa[i], bb[j], acc[i][j]);
    }

    float4 b0 = __ldg((const float4*)bias + tx * 2);
    float4 b1 = __ldg((const float4*)bias + tx * 2 + 1);
#pragma unroll
    for (int i = 0; i < 4; i++) {
        int r0 = base + ty * 8 + i * 2;
        float lo[8], hi[8];
#pragma unroll
        for (int j = 0; j < 8; j++) unpack2(acc[i][j], lo[j], hi[j]);
        if (r0 < n) {
            float4 o0 = make_float4(lo[0] + b0.x, lo[1] + b0.y, lo[2] + b0.z, lo[3] + b0.w);
            float4 o1 = make_float4(lo[4] + b1.x, lo[5] + b1.y, lo[6] + b1.z, lo[7] + b1.w);
            float4* op = (float4*)(out + (size_t)r0 * 128);
            op[tx * 2] = o0; op[tx * 2 + 1] = o1;
        }
        if (r0 + 1 < n) {
            float4 o0 = make_float4(hi[0] + b0.x, hi[1] + b0.y, hi[2] + b0.z, hi[3] + b0.w);
            float4 o1 = make_float4(hi[4] + b1.x, hi[5] + b1.y, hi[6] + b1.z, hi[7] + b1.w);
            float4* op = (float4*)(out + (size_t)(r0 + 1) * 128);
            op[tx * 2] = o0; op[tx * 2 + 1] = o1;
        }
    }
}

__global__ void __launch_bounds__(256, 1) proj3_kernel(
    const float* __restrict__ x,
    const float* __restrict__ Wq, const float* __restrict__ bq,
    const float* __restrict__ Wk, const float* __restrict__ bk,
    const float* __restrict__ Wv, const float* __restrict__ bv, int n)
{
    extern __shared__ float sm[];
    const float *W, *b; float* o;
    if (blockIdx.y == 0)      { W = Wq; b = bq; o = g_q; }
    else if (blockIdx.y == 1) { W = Wk; b = bk; o = g_k; }
    else                      { W = Wv; b = bv; o = g_v; }
    proj_body(x, W, b, o, n, sm, sm + 128 * SROW);
}

__global__ void __launch_bounds__(256, 1) projo_kernel(
    const float* __restrict__ W, const float* __restrict__ b,
    float* __restrict__ out, int n)
{
    extern __shared__ float sm[];
    proj_body(g_agg, W, b, out, n, sm, sm + 128 * SROW);
}

// ---------------------------------------------------------------------------
// node aggregation: one warp per target node, CSR edges, unroll-4 ILP.
// Lane owns float4 j; quad = one head; shfl quad-reduce for dots.
// ---------------------------------------------------------------------------
__device__ __forceinline__ float qdot(float4 a, float4 b)
{
    float s = a.x * b.x + a.y * b.y + a.z * b.z + a.w * b.w;
    s += __shfl_xor_sync(0xFFFFFFFFu, s, 1);
    s += __shfl_xor_sync(0xFFFFFFFFu, s, 2);
    return s;
}

__global__ void __launch_bounds__(256) node_kernel(int n)
{
    int w = (blockIdx.x * blockDim.x + threadIdx.x) >> 5;
    if (w >= n) return;
    int lane = threadIdx.x & 31;

    int beg = __ldg(&g_off[w]);
    int end = __ldg(&g_off[w + 1]);

    float4 kv = __ldg(((const float4*)&g_k[(size_t)w * DIMN]) + lane);

    float4 acc = make_float4(0.f, 0.f, 0.f, 0.f);
    float ssum = 0.f;

    int i = beg;
    for (; i + 4 <= end; i += 4) {
        // batch the index loads, then 8 independent 512B row gathers in flight
        int s0 = __ldg(&g_srcs[i + 0]);
        int s1 = __ldg(&g_srcs[i + 1]);
        int s2 = __ldg(&g_srcs[i + 2]);
        int s3 = __ldg(&g_srcs[i + 3]);
        float4 q0 = __ldg(((const float4*)&g_q[(size_t)s0 * DIMN]) + lane);
        float4 q1 = __ldg(((const float4*)&g_q[(size_t)s1 * DIMN]) + lane);
        float4 q2 = __ldg(((const float4*)&g_q[(size_t)s2 * DIMN]) + lane);
        float4 q3 = __ldg(((const float4*)&g_q[(size_t)s3 * DIMN]) + lane);
        float4 v0 = __ldg(((const float4*)&g_v[(size_t)s0 * DIMN]) + lane);
        float4 v1 = __ldg(((const float4*)&g_v[(size_t)s1 * DIMN]) + lane);
        float4 v2 = __ldg(((const float4*)&g_v[(size_t)s2 * DIMN]) + lane);
        float4 v3 = __ldg(((const float4*)&g_v[(size_t)s3 * DIMN]) + lane);

        float p0 = __expf(qdot(q0, kv) * 0.25f);
        float p1 = __expf(qdot(q1, kv) * 0.25f);
        float p2 = __expf(qdot(q2, kv) * 0.25f);
        float p3 = __expf(qdot(q3, kv) * 0.25f);
        ssum += (p0 + p1) + (p2 + p3);

        acc.x += p0 * v0.x + p1 * v1.x + p2 * v2.x + p3 * v3.x;
        acc.y += p0 * v0.y + p1 * v1.y + p2 * v2.y + p3 * v3.y;
        acc.z += p0 * v0.z + p1 * v1.z + p2 * v2.z + p3 * v3.z;
        acc.w += p0 * v0.w + p1 * v1.w + p2 * v2.w + p3 * v3.w;
    }
    for (; i < end; i++) {
        int s0 = __ldg(&g_srcs[i]);
        float4 q0 = __ldg(((const float4*)&g_q[(size_t)s0 * DIMN]) + lane);
        float4 v0 = __ldg(((const float4*)&g_v[(size_t)s0 * DIMN]) + lane);
        float p0 = __expf(qdot(q0, kv) * 0.25f);
        ssum += p0;
        acc.x += p0 * v0.x; acc.y += p0 * v0.y;
        acc.z += p0 * v0.z; acc.w += p0 * v0.w;
    }

    float inv = (ssum > 0.f) ? __frcp_rn(ssum) : 0.f;
    float4 o = make_float4(acc.x * inv, acc.y * inv, acc.z * inv, acc.w * inv);
    ((float4*)&g_agg[(size_t)w * DIMN])[lane] = o;
}

// ---------------------------------------------------------------------------
extern "C" void kernel_launch(void* const* d_in, const int* in_sizes, int n_in,
                              void* d_out, int out_size)
{
    const float* x   = (const float*)d_in[0];
    const int*   ei  = (const int*)d_in[1];
    const float* Wq  = (const float*)d_in[2];
    const float* bq  = (const float*)d_in[3];
    const float* Wk  = (const float*)d_in[4];
    const float* bk  = (const float*)d_in[5];
    const float* Wv  = (const float*)d_in[6];
    const float* bv  = (const float*)d_in[7];
    const float* Wo  = (const float*)d_in[8];
    const float* bo  = (const float*)d_in[9];
    float*       out = (float*)d_out;

    int n = in_sizes[0] / DIMN;
    int E = in_sizes[1] / 2;

    // side stream + events for overlapping the CSR build with proj3
    // (created once on the first, non-captured, call; same work every call)
    static cudaStream_t s2 = nullptr;
    static cudaEvent_t ev_fork = nullptr, ev_sort = nullptr;
    if (!s2) {
        cudaStreamCreateWithFlags(&s2, cudaStreamNonBlocking);
        cudaEventCreateWithFlags(&ev_fork, cudaEventDisableTiming);
        cudaEventCreateWithFlags(&ev_sort, cudaEventDisableTiming);
    }

    cudaFuncSetAttribute(proj3_kernel, cudaFuncAttributeMaxDynamicSharedMemorySize, PROJ_SMEM);
    cudaFuncSetAttribute(projo_kernel, cudaFuncAttributeMaxDynamicSharedMemorySize, PROJ_SMEM);

    // fork: CSR build on s2, projections on the main stream
    cudaEventRecord(ev_fork, 0);
    cudaStreamWaitEvent(s2, ev_fork, 0);

    init_kernel<<<(n + 255) / 256, 256, 0, s2>>>(n);
    hist_kernel<<<(E + 255) / 256, 256, 0, s2>>>(ei, E);
    scan_kernel<<<1, 1024, 0, s2>>>(n);
    scatter_kernel<<<(E + 255) / 256, 256, 0, s2>>>(ei, E);
    cudaEventRecord(ev_sort, s2);

    int pblocks = (n + 127) / 128;
    proj3_kernel<<<dim3(pblocks, 3), 256, PROJ_SMEM>>>(x, Wq, bq, Wk, bk, Wv, bv, n);

    // join: node aggregation needs both CSR and q/k/v
    cudaStreamWaitEvent(0, ev_sort, 0);
    node_kernel<<<(n * 32 + 255) / 256, 256>>>(n);

    projo_kernel<<<pblocks, 256, PROJ_SMEM>>>(Wo, bo, out, n);
}